// round 7
// baseline (speedup 1.0000x reference)
#include <cuda_runtime.h>
#include <math.h>

#define HWC    65536
#define Bc     8
#define Ec     64
#define Kc     8
#define Sc     4
#define CHUNKS 54            // chunks per image; 8*54 = 432 blocks ~= 2.92/SM
#define PIXPC  1216          // pixels per chunk (mult of 32); last chunk: 1088
#define PHASE  608           // pixels staged per smem phase
#define PAIRSP 304           // pixel-pairs per phase
#define TEMPc  0.2f
#define EPSF   1e-8f

// Per-chunk partial sums/counts + per-(b,k) loss terms. Plain stores (slot per
// block) -> no atomics, no zeroing, no cross-replay state.
__device__ float g_part[Bc * CHUNKS * Kc * Ec];   // [gblk][k][e]
__device__ float g_cntp[Bc * CHUNKS * Kc];        // [gblk][k]
__device__ float g_lterm[Bc * Kc];                // per-(b,k) summed terms

// Packed fp32x2 helpers
#define FFMA2(acc, m, v) \
    asm("fma.rn.f32x2 %0, %1, %2, %0;" : "+l"(acc) : "l"(m), "l"(v))
#define ADDX2(d, a, b) \
    asm("add.rn.f32x2 %0, %1, %2;" : "=l"(d) : "l"(a), "l"(b))
#define PACK2(d, lo, hi) \
    asm("mov.b64 %0, {%1, %2};" : "=l"(d) : "f"(lo), "f"(hi))
#define UNPACK2(lo, hi, s) \
    asm("mov.b64 {%0, %1}, %2;" : "=f"(lo), "=f"(hi) : "l"(s))

// ---------------------------------------------------------------------------
// Sums kernel, 3 CTAs/SM variant. Thread = (channel-pair e2 0..31, pixel
// group g 0..7). Per iter: 2x LDG.128 (2 channel rows, 4 pixels) + 8x LDS.128
// (mask pairs, 1 wavefront each: 8 g-lanes span 128B, broadcast over e2)
// feeding 32 packed FFMA2. Double-buffered mask staging.
// ---------------------------------------------------------------------------
__global__ __launch_bounds__(256, 3) void sums_kernel(
    const float* __restrict__ emb,    // [B,E,HW]
    const float* __restrict__ masks)  // [B,K,HW]
{
    __shared__ __align__(16) float2 sm_m[2][Kc * PAIRSP];  // 38,912 B
    __shared__ float scnt[8][Kc];

    const int tid   = threadIdx.x;
    const int b     = blockIdx.x / CHUNKS;
    const int chunk = blockIdx.x % CHUNKS;
    const int gblk  = blockIdx.x;
    const int n0    = chunk * PIXPC;
    const int npix  = (HWC - n0 < PIXPC) ? (HWC - n0) : PIXPC;  // 1216 or 1088

    const int e2 = tid >> 3;    // 0..31 -> channels 2*e2, 2*e2+1
    const int g  = tid & 7;     // 0..7  -> pixels g*4 .. g*4+3 per 32-px window

    unsigned long long acc[Kc][2];
#pragma unroll
    for (int j = 0; j < Kc; ++j) { acc[j][0] = 0ull; acc[j][1] = 0ull; }

    float msum[Kc];
#pragma unroll
    for (int j = 0; j < Kc; ++j) msum[j] = 0.0f;

    const float* mb = masks + (size_t)b * Kc * HWC;

    const int npx0   = (npix < PHASE) ? npix : PHASE;    // 608
    const int npx1   = npix - npx0;                       // 608 or 480
    const int pairs0 = npx0 >> 1, iters0 = npx0 >> 5;
    const int pairs1 = npx1 >> 1, iters1 = npx1 >> 5;

    // ---- stage phase 0 --------------------------------------------------
#pragma unroll
    for (int j = 0; j < Kc; ++j) {
        const float* mrow = mb + (size_t)j * HWC + n0;
        for (int p = tid; p < pairs0; p += 256) {
            float2 m = *(const float2*)(mrow + 2 * p);
            sm_m[0][j * PAIRSP + p] = m;
            msum[j] += m.x + m.y;
        }
    }
    __syncthreads();

    // ---- stage phase 1 (overlaps compute(0) across warps) ---------------
    if (npx1 > 0) {
#pragma unroll
        for (int j = 0; j < Kc; ++j) {
            const float* mrow = mb + (size_t)j * HWC + n0 + PHASE;
            for (int p = tid; p < pairs1; p += 256) {
                float2 m = *(const float2*)(mrow + 2 * p);
                sm_m[1][j * PAIRSP + p] = m;
                msum[j] += m.x + m.y;
            }
        }
    }

    // ---- compute phase 0 -------------------------------------------------
    {
        const float* eb = emb + ((size_t)(b * Ec + 2 * e2)) * HWC + n0 + g * 4;
#pragma unroll 2
        for (int i = 0; i < iters0; ++i) {
            const int po = i * 32;
            float4 v0 = *(const float4*)(eb + po);
            float4 v1 = *(const float4*)(eb + HWC + po);
            unsigned long long vlo0, vhi0, vlo1, vhi1;
            PACK2(vlo0, v0.x, v0.y); PACK2(vhi0, v0.z, v0.w);
            PACK2(vlo1, v1.x, v1.y); PACK2(vhi1, v1.z, v1.w);
            const int mi = i * 8 + g;   // ulonglong2 index into class row
#pragma unroll
            for (int j = 0; j < Kc; ++j) {
                ulonglong2 mm = *((const ulonglong2*)(sm_m[0] + j * PAIRSP) + mi);
                FFMA2(acc[j][0], mm.x, vlo0);
                FFMA2(acc[j][0], mm.y, vhi0);
                FFMA2(acc[j][1], mm.x, vlo1);
                FFMA2(acc[j][1], mm.y, vhi1);
            }
        }
    }
    __syncthreads();

    // ---- compute phase 1 -------------------------------------------------
    if (npx1 > 0) {
        const float* eb = emb + ((size_t)(b * Ec + 2 * e2)) * HWC
                              + n0 + PHASE + g * 4;
#pragma unroll 2
        for (int i = 0; i < iters1; ++i) {
            const int po = i * 32;
            float4 v0 = *(const float4*)(eb + po);
            float4 v1 = *(const float4*)(eb + HWC + po);
            unsigned long long vlo0, vhi0, vlo1, vhi1;
            PACK2(vlo0, v0.x, v0.y); PACK2(vhi0, v0.z, v0.w);
            PACK2(vlo1, v1.x, v1.y); PACK2(vhi1, v1.z, v1.w);
            const int mi = i * 8 + g;
#pragma unroll
            for (int j = 0; j < Kc; ++j) {
                ulonglong2 mm = *((const ulonglong2*)(sm_m[1] + j * PAIRSP) + mi);
                FFMA2(acc[j][0], mm.x, vlo0);
                FFMA2(acc[j][0], mm.y, vhi0);
                FFMA2(acc[j][1], mm.x, vlo1);
                FFMA2(acc[j][1], mm.y, vhi1);
            }
        }
    }

    // ---- flush sums: reduce over the 8 g-lanes (lane bits 0..2) ---------
#pragma unroll
    for (int j = 0; j < Kc; ++j)
#pragma unroll
        for (int c = 0; c < 2; ++c) {
            unsigned long long a = acc[j][c], o;
            o = __shfl_xor_sync(0xffffffffu, a, 1); ADDX2(a, a, o);
            o = __shfl_xor_sync(0xffffffffu, a, 2); ADDX2(a, a, o);
            o = __shfl_xor_sync(0xffffffffu, a, 4); ADDX2(a, a, o);
            acc[j][c] = a;
        }
    if (g == 0) {
#pragma unroll
        for (int j = 0; j < Kc; ++j)
#pragma unroll
            for (int c = 0; c < 2; ++c) {
                float lo, hi;
                UNPACK2(lo, hi, acc[j][c]);
                g_part[(size_t)gblk * (Kc * Ec) + j * Ec + 2 * e2 + c] = lo + hi;
            }
    }

    // ---- flush counts ---------------------------------------------------
#pragma unroll
    for (int j = 0; j < Kc; ++j) {
        float cnum = msum[j];
        cnum += __shfl_xor_sync(0xffffffffu, cnum, 16);
        cnum += __shfl_xor_sync(0xffffffffu, cnum, 8);
        cnum += __shfl_xor_sync(0xffffffffu, cnum, 4);
        cnum += __shfl_xor_sync(0xffffffffu, cnum, 2);
        cnum += __shfl_xor_sync(0xffffffffu, cnum, 1);
        if ((tid & 31) == 0) scnt[tid >> 5][j] = cnum;
    }
    __syncthreads();
    if (tid < Kc) {
        float cs = 0.0f;
#pragma unroll
        for (int w = 0; w < 8; ++w) cs += scnt[w][tid];
        g_cntp[gblk * Kc + tid] = cs;
    }
}

// ---------------------------------------------------------------------------
// Loss kernel: 64 blocks (one per (b,k)), 128 threads. Plain-stores its
// per-(b,k) term sum into g_lterm (no atomics on out).
// ---------------------------------------------------------------------------
__global__ __launch_bounds__(128, 8) void loss_kernel(
    const float* __restrict__ emb,   // [B,E,HW]
    const int*   __restrict__ pos)   // [B,K,S]
{
    __shared__ float sm[Kc * Ec];    // means for this b
    __shared__ float snm[Kc];        // 1/(max(||mean||,eps)*TEMP)
    __shared__ float cnt_s[Kc];
    __shared__ float term_s[Sc];

    const int t = threadIdx.x;
    const int b = blockIdx.x >> 3;
    const int k = blockIdx.x & 7;

    if (t < Kc) {
        float cs = 0.0f;
        for (int c = 0; c < CHUNKS; ++c)
            cs += g_cntp[(b * CHUNKS + c) * Kc + t];
        cnt_s[t] = fmaxf(cs, 1.0f);
    }
    __syncthreads();

    // reduce partial sums: thread t owns 4 consecutive (j,e) slots
    float4 s = make_float4(0.f, 0.f, 0.f, 0.f);
    for (int c = 0; c < CHUNKS; ++c) {
        float4 v = *(const float4*)&g_part[((size_t)(b * CHUNKS + c)) * (Kc * Ec) + t * 4];
        s.x += v.x; s.y += v.y; s.z += v.z; s.w += v.w;
    }
    const float inv = 1.0f / cnt_s[t >> 4];
    sm[t * 4 + 0] = s.x * inv;
    sm[t * 4 + 1] = s.y * inv;
    sm[t * 4 + 2] = s.z * inv;
    sm[t * 4 + 3] = s.w * inv;
    __syncthreads();

    if (t < Kc) {
        float ss = 0.0f;
#pragma unroll
        for (int e = 0; e < Ec; ++e) {
            float v = sm[t * Ec + e];
            ss += v * v;
        }
        snm[t] = 1.0f / (fmaxf(sqrtf(ss), EPSF) * TEMPc);
    }
    __syncthreads();

    // warp w handles sample s=w; lane l handles channels 2l, 2l+1
    const int w = t >> 5;
    const int l = t & 31;
    const int pix = pos[(b * Kc + k) * Sc + w];

    const float z0 = emb[((size_t)(b * Ec + 2 * l)) * HWC + pix];
    const float z1 = emb[((size_t)(b * Ec + 2 * l + 1)) * HWC + pix];

    float ss = z0 * z0 + z1 * z1;
#pragma unroll
    for (int off = 16; off > 0; off >>= 1)
        ss += __shfl_xor_sync(0xffffffffu, ss, off);
    const float inz = 1.0f / fmaxf(sqrtf(ss), EPSF);

    float sims[Kc];
    float mx = -1e30f;
#pragma unroll
    for (int c = 0; c < Kc; ++c) {
        float d = z0 * sm[c * Ec + 2 * l] + z1 * sm[c * Ec + 2 * l + 1];
#pragma unroll
        for (int off = 16; off > 0; off >>= 1)
            d += __shfl_xor_sync(0xffffffffu, d, off);
        sims[c] = d * inz * snm[c];
        mx = fmaxf(mx, sims[c]);
    }
    float se = 0.0f;
#pragma unroll
    for (int c = 0; c < Kc; ++c) se += expf(sims[c] - mx);
    const float term = (mx + logf(se)) - sims[k];

    if (l == 0) term_s[w] = term;
    __syncthreads();
    if (t == 0)
        g_lterm[blockIdx.x] = term_s[0] + term_s[1] + term_s[2] + term_s[3];
}

// ---------------------------------------------------------------------------
// Final kernel: one warp reduces the 64 per-(b,k) terms into out[0].
// ---------------------------------------------------------------------------
__global__ void final_kernel(float* __restrict__ out)
{
    const int t = threadIdx.x;   // 32 threads
    float v = g_lterm[t] + g_lterm[t + 32];
#pragma unroll
    for (int off = 16; off > 0; off >>= 1)
        v += __shfl_xor_sync(0xffffffffu, v, off);
    if (t == 0) out[0] = v * (1.0f / 256.0f);
}

// ---------------------------------------------------------------------------
// Pattern [sums, loss, final]: 0-based launch idx 3 (= ncu capture slot)
// is the sums kernel of the second call.
// ---------------------------------------------------------------------------
extern "C" void kernel_launch(void* const* d_in, const int* in_sizes, int n_in,
                              void* d_out, int out_size)
{
    const float* emb   = (const float*)d_in[0];  // [8,64,256,256] f32
    const float* masks = (const float*)d_in[1];  // [8,8,256,256] f32
    const int*   pos   = (const int*)d_in[2];    // [8,8,4] i32

    sums_kernel<<<Bc * CHUNKS, 256>>>(emb, masks);
    loss_kernel<<<Bc * Kc, 128>>>(emb, pos);
    final_kernel<<<1, 32>>>((float*)d_out);
}

// round 9
// speedup vs baseline: 1.1169x; 1.1169x over previous
#include <cuda_runtime.h>
#include <math.h>

#define HWC    65536
#define Bc     8
#define Ec     64
#define Kc     8
#define Sc     4
#define CHUNKS 54            // chunks per image; 8*54 = 432 blocks ~= 2.92/SM
#define PIXPC  1216          // pixels per chunk (mult of 32); last chunk: 1088
#define PAIRSC 608           // float2 pairs per class row in smem
#define TEMPc  0.2f
#define EPSF   1e-8f

// Per-chunk partial sums/counts + per-(b,k) loss terms. Plain stores (slot per
// block) -> no atomics, no zeroing, no cross-replay state.
__device__ float g_part[Bc * CHUNKS * Kc * Ec];   // [gblk][k][e]
__device__ float g_cntp[Bc * CHUNKS * Kc];        // [gblk][k]
__device__ float g_lterm[Bc * Kc];                // per-(b,k) summed terms

// Packed fp32x2 helpers
#define FFMA2(acc, m, v) \
    asm("fma.rn.f32x2 %0, %1, %2, %0;" : "+l"(acc) : "l"(m), "l"(v))
#define ADDX2(d, a, b) \
    asm("add.rn.f32x2 %0, %1, %2;" : "=l"(d) : "l"(a), "l"(b))
#define PACK2(d, lo, hi) \
    asm("mov.b64 %0, {%1, %2};" : "=l"(d) : "f"(lo), "f"(hi))
#define UNPACK2(lo, hi, s) \
    asm("mov.b64 {%0, %1}, %2;" : "=f"(lo), "=f"(hi) : "l"(s))

// ---------------------------------------------------------------------------
// Sums kernel, 3 CTAs/SM, software-pipelined embedding loads.
// Thread = (channel-pair e2 0..31, pixel group g 0..7). Whole-chunk mask
// staging (single buffer, one sync). Compute loop: pack iter i, prefetch
// iter i+1's 2x LDG.128, then 8x{LDS.128 + 4 FFMA2}.
// ---------------------------------------------------------------------------
__global__ __launch_bounds__(256, 3) void sums_kernel(
    const float* __restrict__ emb,    // [B,E,HW]
    const float* __restrict__ masks)  // [B,K,HW]
{
    __shared__ __align__(16) float2 sm_m[Kc * PAIRSC];   // 38,912 B
    __shared__ float scnt[8][Kc];

    const int tid   = threadIdx.x;
    const int b     = blockIdx.x / CHUNKS;
    const int chunk = blockIdx.x % CHUNKS;
    const int gblk  = blockIdx.x;
    const int n0    = chunk * PIXPC;
    const int npix  = (HWC - n0 < PIXPC) ? (HWC - n0) : PIXPC;  // 1216 or 1088

    const int e2 = tid >> 3;    // 0..31 -> channels 2*e2, 2*e2+1
    const int g  = tid & 7;     // 0..7  -> pixels g*4..g*4+3 per 32-px window

    unsigned long long acc[Kc][2];
#pragma unroll
    for (int j = 0; j < Kc; ++j) { acc[j][0] = 0ull; acc[j][1] = 0ull; }

    float msum[Kc];
#pragma unroll
    for (int j = 0; j < Kc; ++j) msum[j] = 0.0f;

    // ---- stage masks for the whole chunk (float4-wide, batched) ---------
    const float* mb = masks + (size_t)b * Kc * HWC + n0;
    const int nq = npix >> 2;            // float4s per class row: 304 or 272
#pragma unroll
    for (int j = 0; j < Kc; ++j) {
        const float4* mrow = (const float4*)(mb + (size_t)j * HWC);
        float4* srow = (float4*)(sm_m + j * PAIRSC);
        for (int p = tid; p < nq; p += 256) {
            float4 m = mrow[p];
            srow[p] = m;
            msum[j] += (m.x + m.y) + (m.z + m.w);
        }
    }
    __syncthreads();

    // ---- compute: 1-deep prefetch pipeline ------------------------------
    {
        const float* eb = emb + ((size_t)(b * Ec + 2 * e2)) * HWC + n0 + g * 4;
        const int iters = npix >> 5;     // 38 or 34

        float4 v0 = *(const float4*)(eb);
        float4 v1 = *(const float4*)(eb + HWC);

        for (int i = 0; i < iters; ++i) {
            // pack current values first (frees v0/v1 for the prefetch)
            unsigned long long a0, a1, c0, c1;
            PACK2(a0, v0.x, v0.y); PACK2(a1, v0.z, v0.w);
            PACK2(c0, v1.x, v1.y); PACK2(c1, v1.z, v1.w);

            // prefetch next iteration's embeddings (in flight during FFMA2s)
            if (i + 1 < iters) {
                const int po = (i + 1) * 32;
                v0 = *(const float4*)(eb + po);
                v1 = *(const float4*)(eb + HWC + po);
            }

            const ulonglong2* mrow = (const ulonglong2*)sm_m;
            const int mi = i * 8 + g;    // 16B units within a class row
#pragma unroll
            for (int j = 0; j < Kc; ++j) {
                ulonglong2 mm = mrow[j * (PAIRSC / 2) + mi];
                FFMA2(acc[j][0], mm.x, a0);
                FFMA2(acc[j][0], mm.y, a1);
                FFMA2(acc[j][1], mm.x, c0);
                FFMA2(acc[j][1], mm.y, c1);
            }
        }
    }

    // ---- flush sums: reduce over the 8 g-lanes (lane bits 0..2) ---------
#pragma unroll
    for (int j = 0; j < Kc; ++j)
#pragma unroll
        for (int c = 0; c < 2; ++c) {
            unsigned long long a = acc[j][c], o;
            o = __shfl_xor_sync(0xffffffffu, a, 1); ADDX2(a, a, o);
            o = __shfl_xor_sync(0xffffffffu, a, 2); ADDX2(a, a, o);
            o = __shfl_xor_sync(0xffffffffu, a, 4); ADDX2(a, a, o);
            acc[j][c] = a;
        }
    if (g == 0) {
#pragma unroll
        for (int j = 0; j < Kc; ++j)
#pragma unroll
            for (int c = 0; c < 2; ++c) {
                float lo, hi;
                UNPACK2(lo, hi, acc[j][c]);
                g_part[(size_t)gblk * (Kc * Ec) + j * Ec + 2 * e2 + c] = lo + hi;
            }
    }

    // ---- flush counts ---------------------------------------------------
#pragma unroll
    for (int j = 0; j < Kc; ++j) {
        float cnum = msum[j];
        cnum += __shfl_xor_sync(0xffffffffu, cnum, 16);
        cnum += __shfl_xor_sync(0xffffffffu, cnum, 8);
        cnum += __shfl_xor_sync(0xffffffffu, cnum, 4);
        cnum += __shfl_xor_sync(0xffffffffu, cnum, 2);
        cnum += __shfl_xor_sync(0xffffffffu, cnum, 1);
        if ((tid & 31) == 0) scnt[tid >> 5][j] = cnum;
    }
    __syncthreads();
    if (tid < Kc) {
        float cs = 0.0f;
#pragma unroll
        for (int w = 0; w < 8; ++w) cs += scnt[w][tid];
        g_cntp[gblk * Kc + tid] = cs;
    }
}

// ---------------------------------------------------------------------------
// Loss kernel: 64 blocks (one per (b,k)), 128 threads. Plain-stores its
// per-(b,k) term sum into g_lterm (no atomics on out).
// ---------------------------------------------------------------------------
__global__ __launch_bounds__(128, 8) void loss_kernel(
    const float* __restrict__ emb,   // [B,E,HW]
    const int*   __restrict__ pos)   // [B,K,S]
{
    __shared__ float sm[Kc * Ec];    // means for this b
    __shared__ float snm[Kc];        // 1/(max(||mean||,eps)*TEMP)
    __shared__ float cnt_s[Kc];
    __shared__ float term_s[Sc];

    const int t = threadIdx.x;
    const int b = blockIdx.x >> 3;
    const int k = blockIdx.x & 7;

    if (t < Kc) {
        float cs = 0.0f;
        for (int c = 0; c < CHUNKS; ++c)
            cs += g_cntp[(b * CHUNKS + c) * Kc + t];
        cnt_s[t] = fmaxf(cs, 1.0f);
    }
    __syncthreads();

    // reduce partial sums: thread t owns 4 consecutive (j,e) slots
    float4 s = make_float4(0.f, 0.f, 0.f, 0.f);
    for (int c = 0; c < CHUNKS; ++c) {
        float4 v = *(const float4*)&g_part[((size_t)(b * CHUNKS + c)) * (Kc * Ec) + t * 4];
        s.x += v.x; s.y += v.y; s.z += v.z; s.w += v.w;
    }
    const float inv = 1.0f / cnt_s[t >> 4];
    sm[t * 4 + 0] = s.x * inv;
    sm[t * 4 + 1] = s.y * inv;
    sm[t * 4 + 2] = s.z * inv;
    sm[t * 4 + 3] = s.w * inv;
    __syncthreads();

    if (t < Kc) {
        float ss = 0.0f;
#pragma unroll
        for (int e = 0; e < Ec; ++e) {
            float v = sm[t * Ec + e];
            ss += v * v;
        }
        snm[t] = 1.0f / (fmaxf(sqrtf(ss), EPSF) * TEMPc);
    }
    __syncthreads();

    // warp w handles sample s=w; lane l handles channels 2l, 2l+1
    const int w = t >> 5;
    const int l = t & 31;
    const int pix = pos[(b * Kc + k) * Sc + w];

    const float z0 = emb[((size_t)(b * Ec + 2 * l)) * HWC + pix];
    const float z1 = emb[((size_t)(b * Ec + 2 * l + 1)) * HWC + pix];

    float ss = z0 * z0 + z1 * z1;
#pragma unroll
    for (int off = 16; off > 0; off >>= 1)
        ss += __shfl_xor_sync(0xffffffffu, ss, off);
    const float inz = 1.0f / fmaxf(sqrtf(ss), EPSF);

    float sims[Kc];
    float mx = -1e30f;
#pragma unroll
    for (int c = 0; c < Kc; ++c) {
        float d = z0 * sm[c * Ec + 2 * l] + z1 * sm[c * Ec + 2 * l + 1];
#pragma unroll
        for (int off = 16; off > 0; off >>= 1)
            d += __shfl_xor_sync(0xffffffffu, d, off);
        sims[c] = d * inz * snm[c];
        mx = fmaxf(mx, sims[c]);
    }
    float se = 0.0f;
#pragma unroll
    for (int c = 0; c < Kc; ++c) se += expf(sims[c] - mx);
    const float term = (mx + logf(se)) - sims[k];

    if (l == 0) term_s[w] = term;
    __syncthreads();
    if (t == 0)
        g_lterm[blockIdx.x] = term_s[0] + term_s[1] + term_s[2] + term_s[3];
}

// ---------------------------------------------------------------------------
// Final kernel: one warp reduces the 64 per-(b,k) terms into out[0].
// ---------------------------------------------------------------------------
__global__ void final_kernel(float* __restrict__ out)
{
    const int t = threadIdx.x;   // 32 threads
    float v = g_lterm[t] + g_lterm[t + 32];
#pragma unroll
    for (int off = 16; off > 0; off >>= 1)
        v += __shfl_xor_sync(0xffffffffu, v, off);
    if (t == 0) out[0] = v * (1.0f / 256.0f);
}

// ---------------------------------------------------------------------------
// Pattern [sums, loss, final]: 0-based launch idx 3 (= ncu capture slot)
// is the sums kernel of the second call.
// ---------------------------------------------------------------------------
extern "C" void kernel_launch(void* const* d_in, const int* in_sizes, int n_in,
                              void* d_out, int out_size)
{
    const float* emb   = (const float*)d_in[0];  // [8,64,256,256] f32
    const float* masks = (const float*)d_in[1];  // [8,8,256,256] f32
    const int*   pos   = (const int*)d_in[2];    // [8,8,4] i32

    sums_kernel<<<Bc * CHUNKS, 256>>>(emb, masks);
    loss_kernel<<<Bc * Kc, 128>>>(emb, pos);
    final_kernel<<<1, 32>>>((float*)d_out);
}

// round 10
// speedup vs baseline: 1.3008x; 1.1646x over previous
#include <cuda_runtime.h>
#include <math.h>

#define HWC    65536
#define Bc     8
#define Ec     64
#define Kc     8
#define Sc     4
#define CHUNKS 54            // chunks per image; 8*54 = 432 blocks ~= 2.92/SM
#define PIXPC  1216          // pixels per chunk (mult of 64); last chunk: 1088
#define PAIRSC 608           // float2 pairs per class row in smem
#define STPX   64            // pixels per cp.async stage
#define STBYTES (STPX * Ec * 4)        // 16,384 B per stage
#define SM_MASK 38912                  // Kc * PAIRSC * 8
#define SM_EMB  SM_MASK                // emb stages at this offset (2 stages)
#define SM_CNT  (SM_MASK + 2 * STBYTES)          // 71,680
#define SMEM_TOTAL (SM_CNT + 8 * Kc * 4)         // 71,936
#define TEMPc  0.2f
#define EPSF   1e-8f

// Per-chunk partial sums/counts + per-(b,k) loss terms. Plain stores (slot per
// block) -> no atomics, no zeroing, no cross-replay state.
__device__ float g_part[Bc * CHUNKS * Kc * Ec];   // [gblk][k][e]
__device__ float g_cntp[Bc * CHUNKS * Kc];        // [gblk][k]
__device__ float g_lterm[Bc * Kc];                // per-(b,k) summed terms

// Packed fp32x2 helpers
#define FFMA2(acc, m, v) \
    asm("fma.rn.f32x2 %0, %1, %2, %0;" : "+l"(acc) : "l"(m), "l"(v))
#define ADDX2(d, a, b) \
    asm("add.rn.f32x2 %0, %1, %2;" : "=l"(d) : "l"(a), "l"(b))
#define PACK2(d, lo, hi) \
    asm("mov.b64 %0, {%1, %2};" : "=l"(d) : "f"(lo), "f"(hi))
#define UNPACK2(lo, hi, s) \
    asm("mov.b64 {%0, %1}, %2;" : "=f"(lo), "=f"(hi) : "l"(s))

#define CP_ASYNC16(sp, gp) \
    asm volatile("cp.async.cg.shared.global [%0], [%1], 16;" :: "r"(sp), "l"(gp))
#define CP_COMMIT() asm volatile("cp.async.commit_group;")
#define CP_WAIT1()  asm volatile("cp.async.wait_group 1;")

// ---------------------------------------------------------------------------
// Sums kernel, 3 CTAs/SM. Embeddings flow through a 2-stage cp.async smem
// pipeline (16 KB/stage): in-flight bytes live in smem, not registers, so
// MLP is no longer register-capped. Masks staged whole-chunk as before.
// Compute per 32 px: 2 emb LDS.128 + 8 mask LDS.128 (broadcast) + 32 FFMA2.
// ---------------------------------------------------------------------------
__global__ __launch_bounds__(256, 3) void sums_kernel(
    const float* __restrict__ emb,    // [B,E,HW]
    const float* __restrict__ masks)  // [B,K,HW]
{
    extern __shared__ __align__(16) unsigned char smraw[];
    float2* sm_m = (float2*)smraw;                       // [Kc*PAIRSC]
    float*  sm_e = (float*)(smraw + SM_EMB);             // [2][Ec*STPX]
    float (*scnt)[Kc] = (float (*)[Kc])(smraw + SM_CNT);

    const int tid   = threadIdx.x;
    const int b     = blockIdx.x / CHUNKS;
    const int chunk = blockIdx.x % CHUNKS;
    const int gblk  = blockIdx.x;
    const int n0    = chunk * PIXPC;
    const int npix  = (HWC - n0 < PIXPC) ? (HWC - n0) : PIXPC;  // 1216 or 1088
    const int nst   = npix >> 6;                                 // 19 or 17

    const int e2 = tid >> 3;    // 0..31 -> channels 2*e2, 2*e2+1
    const int g  = tid & 7;     // 0..7  -> pixels g*4..g*4+3 per 32-px window

    unsigned long long acc[Kc][2];
#pragma unroll
    for (int j = 0; j < Kc; ++j) { acc[j][0] = 0ull; acc[j][1] = 0ull; }

    float msum[Kc];
#pragma unroll
    for (int j = 0; j < Kc; ++j) msum[j] = 0.0f;

    const float* eb = emb + (size_t)b * Ec * HWC + n0;
    const unsigned sm_e_u32 = (unsigned)__cvta_generic_to_shared(sm_e);

    // cp.async addressing for one stage: 1024 x 16B chunks, idx -> (ch, seg)
    // smem: stage + ch*256 + seg*16 ; global: eb + ch*HWC + st*64 + seg*4
#define ISSUE_STAGE(st) do {                                               \
        const unsigned sb_ = sm_e_u32 + ((st) & 1) * STBYTES;              \
        const float* gb_ = eb + (st) * STPX;                               \
        _Pragma("unroll")                                                  \
        for (int r_ = 0; r_ < 4; ++r_) {                                   \
            int idx_ = r_ * 256 + tid;                                     \
            int ch_  = idx_ >> 4;                                          \
            int seg_ = idx_ & 15;                                          \
            CP_ASYNC16(sb_ + idx_ * 16, gb_ + (size_t)ch_ * HWC + seg_ * 4);\
        }                                                                  \
    } while (0)

    // ---- prologue: start emb stages 0 and 1 -----------------------------
    ISSUE_STAGE(0); CP_COMMIT();
    ISSUE_STAGE(1); CP_COMMIT();

    // ---- stage masks for the whole chunk (float4-wide, batched) ---------
    const float* mb = masks + (size_t)b * Kc * HWC + n0;
    const int nq = npix >> 2;            // float4s per class row
#pragma unroll
    for (int j = 0; j < Kc; ++j) {
        const float4* mrow = (const float4*)(mb + (size_t)j * HWC);
        float4* srow = (float4*)(sm_m + j * PAIRSC);
        for (int p = tid; p < nq; p += 256) {
            float4 m = mrow[p];
            srow[p] = m;
            msum[j] += (m.x + m.y) + (m.z + m.w);
        }
    }

    // ---- pipelined compute over 64-px stages ----------------------------
    const ulonglong2* mrow = (const ulonglong2*)sm_m;
    for (int s = 0; s < nst; ++s) {
        CP_WAIT1();            // stage s complete (all groups but newest 1)
        __syncthreads();       // cross-thread visibility of stage s

        const float* sb = sm_e + (s & 1) * (STBYTES / 4) + (2 * e2) * STPX + g * 4;
#pragma unroll
        for (int h = 0; h < 2; ++h) {
            float4 v0 = *(const float4*)(sb + h * 32);
            float4 v1 = *(const float4*)(sb + STPX + h * 32);
            unsigned long long a0, a1, c0, c1;
            PACK2(a0, v0.x, v0.y); PACK2(a1, v0.z, v0.w);
            PACK2(c0, v1.x, v1.y); PACK2(c1, v1.z, v1.w);
            const int mi = s * 16 + h * 8 + g;   // 16B units in class row
#pragma unroll
            for (int j = 0; j < Kc; ++j) {
                ulonglong2 mm = mrow[j * (PAIRSC / 2) + mi];
                FFMA2(acc[j][0], mm.x, a0);
                FFMA2(acc[j][0], mm.y, a1);
                FFMA2(acc[j][1], mm.x, c0);
                FFMA2(acc[j][1], mm.y, c1);
            }
        }
        __syncthreads();       // all warps done with buffer (s&1) before refill

        if (s + 2 < nst) ISSUE_STAGE(s + 2);
        CP_COMMIT();           // always commit (dummy at tail keeps invariant)
    }

    // ---- flush sums: reduce over the 8 g-lanes (lane bits 0..2) ---------
#pragma unroll
    for (int j = 0; j < Kc; ++j)
#pragma unroll
        for (int c = 0; c < 2; ++c) {
            unsigned long long a = acc[j][c], o;
            o = __shfl_xor_sync(0xffffffffu, a, 1); ADDX2(a, a, o);
            o = __shfl_xor_sync(0xffffffffu, a, 2); ADDX2(a, a, o);
            o = __shfl_xor_sync(0xffffffffu, a, 4); ADDX2(a, a, o);
            acc[j][c] = a;
        }
    if (g == 0) {
#pragma unroll
        for (int j = 0; j < Kc; ++j)
#pragma unroll
            for (int c = 0; c < 2; ++c) {
                float lo, hi;
                UNPACK2(lo, hi, acc[j][c]);
                g_part[(size_t)gblk * (Kc * Ec) + j * Ec + 2 * e2 + c] = lo + hi;
            }
    }

    // ---- flush counts ---------------------------------------------------
#pragma unroll
    for (int j = 0; j < Kc; ++j) {
        float cnum = msum[j];
        cnum += __shfl_xor_sync(0xffffffffu, cnum, 16);
        cnum += __shfl_xor_sync(0xffffffffu, cnum, 8);
        cnum += __shfl_xor_sync(0xffffffffu, cnum, 4);
        cnum += __shfl_xor_sync(0xffffffffu, cnum, 2);
        cnum += __shfl_xor_sync(0xffffffffu, cnum, 1);
        if ((tid & 31) == 0) scnt[tid >> 5][j] = cnum;
    }
    __syncthreads();
    if (tid < Kc) {
        float cs = 0.0f;
#pragma unroll
        for (int w = 0; w < 8; ++w) cs += scnt[w][tid];
        g_cntp[gblk * Kc + tid] = cs;
    }
#undef ISSUE_STAGE
}

// ---------------------------------------------------------------------------
// Loss kernel: 64 blocks (one per (b,k)), 128 threads. Plain-stores its
// per-(b,k) term sum into g_lterm (no atomics on out).
// ---------------------------------------------------------------------------
__global__ __launch_bounds__(128, 8) void loss_kernel(
    const float* __restrict__ emb,   // [B,E,HW]
    const int*   __restrict__ pos)   // [B,K,S]
{
    __shared__ float sm[Kc * Ec];    // means for this b
    __shared__ float snm[Kc];        // 1/(max(||mean||,eps)*TEMP)
    __shared__ float cnt_s[Kc];
    __shared__ float term_s[Sc];

    const int t = threadIdx.x;
    const int b = blockIdx.x >> 3;
    const int k = blockIdx.x & 7;

    if (t < Kc) {
        float cs = 0.0f;
        for (int c = 0; c < CHUNKS; ++c)
            cs += g_cntp[(b * CHUNKS + c) * Kc + t];
        cnt_s[t] = fmaxf(cs, 1.0f);
    }
    __syncthreads();

    // reduce partial sums: thread t owns 4 consecutive (j,e) slots
    float4 s = make_float4(0.f, 0.f, 0.f, 0.f);
    for (int c = 0; c < CHUNKS; ++c) {
        float4 v = *(const float4*)&g_part[((size_t)(b * CHUNKS + c)) * (Kc * Ec) + t * 4];
        s.x += v.x; s.y += v.y; s.z += v.z; s.w += v.w;
    }
    const float inv = 1.0f / cnt_s[t >> 4];
    sm[t * 4 + 0] = s.x * inv;
    sm[t * 4 + 1] = s.y * inv;
    sm[t * 4 + 2] = s.z * inv;
    sm[t * 4 + 3] = s.w * inv;
    __syncthreads();

    if (t < Kc) {
        float ss = 0.0f;
#pragma unroll
        for (int e = 0; e < Ec; ++e) {
            float v = sm[t * Ec + e];
            ss += v * v;
        }
        snm[t] = 1.0f / (fmaxf(sqrtf(ss), EPSF) * TEMPc);
    }
    __syncthreads();

    // warp w handles sample s=w; lane l handles channels 2l, 2l+1
    const int w = t >> 5;
    const int l = t & 31;
    const int pix = pos[(b * Kc + k) * Sc + w];

    const float z0 = emb[((size_t)(b * Ec + 2 * l)) * HWC + pix];
    const float z1 = emb[((size_t)(b * Ec + 2 * l + 1)) * HWC + pix];

    float ss = z0 * z0 + z1 * z1;
#pragma unroll
    for (int off = 16; off > 0; off >>= 1)
        ss += __shfl_xor_sync(0xffffffffu, ss, off);
    const float inz = 1.0f / fmaxf(sqrtf(ss), EPSF);

    float sims[Kc];
    float mx = -1e30f;
#pragma unroll
    for (int c = 0; c < Kc; ++c) {
        float d = z0 * sm[c * Ec + 2 * l] + z1 * sm[c * Ec + 2 * l + 1];
#pragma unroll
        for (int off = 16; off > 0; off >>= 1)
            d += __shfl_xor_sync(0xffffffffu, d, off);
        sims[c] = d * inz * snm[c];
        mx = fmaxf(mx, sims[c]);
    }
    float se = 0.0f;
#pragma unroll
    for (int c = 0; c < Kc; ++c) se += expf(sims[c] - mx);
    const float term = (mx + logf(se)) - sims[k];

    if (l == 0) term_s[w] = term;
    __syncthreads();
    if (t == 0)
        g_lterm[blockIdx.x] = term_s[0] + term_s[1] + term_s[2] + term_s[3];
}

// ---------------------------------------------------------------------------
// Final kernel: one warp reduces the 64 per-(b,k) terms into out[0].
// ---------------------------------------------------------------------------
__global__ void final_kernel(float* __restrict__ out)
{
    const int t = threadIdx.x;   // 32 threads
    float v = g_lterm[t] + g_lterm[t + 32];
#pragma unroll
    for (int off = 16; off > 0; off >>= 1)
        v += __shfl_xor_sync(0xffffffffu, v, off);
    if (t == 0) out[0] = v * (1.0f / 256.0f);
}

// ---------------------------------------------------------------------------
// Pattern [sums, loss, final]: 0-based launch idx 3 (= ncu capture slot)
// is the sums kernel of the second call.
// ---------------------------------------------------------------------------
extern "C" void kernel_launch(void* const* d_in, const int* in_sizes, int n_in,
                              void* d_out, int out_size)
{
    const float* emb   = (const float*)d_in[0];  // [8,64,256,256] f32
    const float* masks = (const float*)d_in[1];  // [8,8,256,256] f32
    const int*   pos   = (const int*)d_in[2];    // [8,8,4] i32

    // Attribute set (not an allocation); idempotent, executes immediately.
    cudaFuncSetAttribute(sums_kernel,
                         cudaFuncAttributeMaxDynamicSharedMemorySize, SMEM_TOTAL);

    sums_kernel<<<Bc * CHUNKS, 256, SMEM_TOTAL>>>(emb, masks);
    loss_kernel<<<Bc * Kc, 128>>>(emb, pos);
    final_kernel<<<1, 32>>>((float*)d_out);
}

// round 13
// speedup vs baseline: 1.4296x; 1.0990x over previous
#include <cuda_runtime.h>
#include <math.h>

#define HWC    65536
#define Bc     8
#define Ec     64
#define Kc     8
#define Sc     4
#define CHUNKS 54            // chunks per image; 8*54 = 432 blocks ~= 2.92/SM
#define PIXPC  1216          // pixels per chunk (mult of 64); last chunk: 1088
#define STPX   64            // pixels per pipeline stage
#define EMB_ST (STPX * Ec * 4)          // 16,384 B emb per stage
#define MSK_ST (STPX * Kc * 4)          //  2,048 B mask per stage
#define STAGE  (EMB_ST + MSK_ST)        // 18,432 B per stage
#define NST    3                        // ring depth
#define SMEM_TOTAL (NST * STAGE)        // 55,296 B
#define TEMPc  0.2f
#define EPSF   1e-8f

// Per-chunk partial sums/counts + per-(b,k) loss terms. Plain stores (slot per
// block) -> no atomics, no zeroing, no cross-replay state.
__device__ float g_part[Bc * CHUNKS * Kc * Ec];   // [gblk][k][e]
__device__ float g_cntp[Bc * CHUNKS * Kc];        // [gblk][k]
__device__ float g_lterm[Bc * Kc];                // per-(b,k) summed terms

// Packed fp32x2 helpers
#define FFMA2(acc, m, v) \
    asm("fma.rn.f32x2 %0, %1, %2, %0;" : "+l"(acc) : "l"(m), "l"(v))
#define ADDX2(d, a, b) \
    asm("add.rn.f32x2 %0, %1, %2;" : "=l"(d) : "l"(a), "l"(b))
#define PACK2(d, lo, hi) \
    asm("mov.b64 %0, {%1, %2};" : "=l"(d) : "f"(lo), "f"(hi))
#define UNPACK2(lo, hi, s) \
    asm("mov.b64 {%0, %1}, %2;" : "=f"(lo), "=f"(hi) : "l"(s))

#define CP_ASYNC16(sp, gp) \
    asm volatile("cp.async.cg.shared.global [%0], [%1], 16;" :: "r"(sp), "l"(gp))
#define CP_COMMIT() asm volatile("cp.async.commit_group;")
#define CP_WAIT2()  asm volatile("cp.async.wait_group 2;")

// ---------------------------------------------------------------------------
// Sums kernel, 3 CTAs/SM. 3-stage cp.async ring; each stage carries BOTH the
// 64-px embedding tile (16 KB) and its 8-class mask slice (2 KB). Two full
// stages stay in flight during compute (wait_group 2) -> ~108 KB/SM of
// outstanding DRAM traffic. Class counts fold into the compute loop: warp w
// accumulates class w from the mask values already in smem (x4 lane
// duplication divided out at flush).
// ---------------------------------------------------------------------------
__global__ __launch_bounds__(256, 3) void sums_kernel(
    const float* __restrict__ emb,    // [B,E,HW]
    const float* __restrict__ masks)  // [B,K,HW]
{
    extern __shared__ __align__(16) unsigned char smraw[];

    const int tid   = threadIdx.x;
    const int b     = blockIdx.x / CHUNKS;
    const int chunk = blockIdx.x % CHUNKS;
    const int gblk  = blockIdx.x;
    const int n0    = chunk * PIXPC;
    const int npix  = (HWC - n0 < PIXPC) ? (HWC - n0) : PIXPC;  // 1216 or 1088
    const int nst   = npix >> 6;                                 // 19 or 17

    const int e2 = tid >> 3;    // 0..31 -> channels 2*e2, 2*e2+1
    const int g  = tid & 7;     // 0..7  -> pixels g*4..g*4+3 per 32-px window
    const int w  = tid >> 5;    // warp id == class owned for counting

    unsigned long long acc[Kc][2];
#pragma unroll
    for (int j = 0; j < Kc; ++j) { acc[j][0] = 0ull; acc[j][1] = 0ull; }
    unsigned long long cnt = 0ull;

    const float* eb = emb   + (size_t)b * Ec * HWC + n0;
    const float* mb = masks + (size_t)b * Kc * HWC + n0;
    const unsigned sm_u32 = (unsigned)__cvta_generic_to_shared(smraw);

    // One stage: emb 1024x16B chunks (4/thread) + mask 128x16B chunks
    // (threads 0..127). smem emb layout [ch][64px]; mask [cls][64px].
#define ISSUE_STAGE(st) do {                                                 \
        const int sl_ = (st) % NST;                                          \
        const unsigned sb_ = sm_u32 + sl_ * STAGE;                           \
        const float* gb_ = eb + (st) * STPX;                                 \
        _Pragma("unroll")                                                    \
        for (int r_ = 0; r_ < 4; ++r_) {                                     \
            int idx_ = r_ * 256 + tid;                                       \
            int ch_  = idx_ >> 4;                                            \
            int seg_ = idx_ & 15;                                            \
            CP_ASYNC16(sb_ + idx_ * 16, gb_ + (size_t)ch_ * HWC + seg_ * 4); \
        }                                                                    \
        if (tid < 128) {                                                     \
            int k_   = tid >> 4;                                             \
            int seg_ = tid & 15;                                             \
            CP_ASYNC16(sb_ + EMB_ST + tid * 16,                              \
                       mb + (st) * STPX + (size_t)k_ * HWC + seg_ * 4);      \
        }                                                                    \
    } while (0)

    // ---- prologue: fill the ring ---------------------------------------
    ISSUE_STAGE(0); CP_COMMIT();
    ISSUE_STAGE(1); CP_COMMIT();
    ISSUE_STAGE(2); CP_COMMIT();

    // ---- pipelined compute over 64-px stages ----------------------------
    for (int s = 0; s < nst; ++s) {
        CP_WAIT2();            // stage s complete (<=2 newer groups pending)
        __syncthreads();       // cross-thread visibility of stage s

        const unsigned char* base = smraw + (s % NST) * STAGE;
        const float* se = (const float*)base + (2 * e2) * STPX + g * 4;
        const ulonglong2* sm = (const ulonglong2*)(base + EMB_ST);  // [cls][16]

#pragma unroll
        for (int h = 0; h < 2; ++h) {
            float4 v0 = *(const float4*)(se + h * 32);
            float4 v1 = *(const float4*)(se + STPX + h * 32);
            unsigned long long a0, a1, c0, c1;
            PACK2(a0, v0.x, v0.y); PACK2(a1, v0.z, v0.w);
            PACK2(c0, v1.x, v1.y); PACK2(c1, v1.z, v1.w);
            const int mi = h * 8 + g;   // 16B units within a class row
#pragma unroll
            for (int j = 0; j < Kc; ++j) {
                ulonglong2 mm = sm[j * 16 + mi];
                FFMA2(acc[j][0], mm.x, a0);
                FFMA2(acc[j][0], mm.y, a1);
                FFMA2(acc[j][1], mm.x, c0);
                FFMA2(acc[j][1], mm.y, c1);
            }
            // counts: warp w owns class w (1 broadcast LDS + 2 packed adds)
            ulonglong2 mw = sm[w * 16 + mi];
            ADDX2(cnt, cnt, mw.x);
            ADDX2(cnt, cnt, mw.y);
        }
        __syncthreads();       // all warps done with buffer (s%NST)

        if (s + NST < nst) ISSUE_STAGE(s + NST);
        CP_COMMIT();           // always commit (empty at tail keeps invariant)
    }

    // ---- flush sums: reduce over the 8 g-lanes (lane bits 0..2) ---------
#pragma unroll
    for (int j = 0; j < Kc; ++j)
#pragma unroll
        for (int c = 0; c < 2; ++c) {
            unsigned long long a = acc[j][c], o;
            o = __shfl_xor_sync(0xffffffffu, a, 1); ADDX2(a, a, o);
            o = __shfl_xor_sync(0xffffffffu, a, 2); ADDX2(a, a, o);
            o = __shfl_xor_sync(0xffffffffu, a, 4); ADDX2(a, a, o);
            acc[j][c] = a;
        }
    if (g == 0) {
#pragma unroll
        for (int j = 0; j < Kc; ++j)
#pragma unroll
            for (int c = 0; c < 2; ++c) {
                float lo, hi;
                UNPACK2(lo, hi, acc[j][c]);
                g_part[(size_t)gblk * (Kc * Ec) + j * Ec + 2 * e2 + c] = lo + hi;
            }
    }

    // ---- flush counts: reduce cnt over the warp, /4 lane duplication ----
    {
        unsigned long long a = cnt, o;
        o = __shfl_xor_sync(0xffffffffu, a, 1);  ADDX2(a, a, o);
        o = __shfl_xor_sync(0xffffffffu, a, 2);  ADDX2(a, a, o);
        o = __shfl_xor_sync(0xffffffffu, a, 4);  ADDX2(a, a, o);
        o = __shfl_xor_sync(0xffffffffu, a, 8);  ADDX2(a, a, o);
        o = __shfl_xor_sync(0xffffffffu, a, 16); ADDX2(a, a, o);
        if ((tid & 31) == 0) {
            float lo, hi;
            UNPACK2(lo, hi, a);
            g_cntp[gblk * Kc + w] = (lo + hi) * 0.25f;
        }
    }
#undef ISSUE_STAGE
}

// ---------------------------------------------------------------------------
// Loss kernel: 64 blocks (one per (b,k)), 128 threads. Plain-stores its
// per-(b,k) term sum into g_lterm (no atomics on out).
// ---------------------------------------------------------------------------
__global__ __launch_bounds__(128, 8) void loss_kernel(
    const float* __restrict__ emb,   // [B,E,HW]
    const int*   __restrict__ pos)   // [B,K,S]
{
    __shared__ float sm[Kc * Ec];    // means for this b
    __shared__ float snm[Kc];        // 1/(max(||mean||,eps)*TEMP)
    __shared__ float cnt_s[Kc];
    __shared__ float term_s[Sc];

    const int t = threadIdx.x;
    const int b = blockIdx.x >> 3;
    const int k = blockIdx.x & 7;

    if (t < Kc) {
        float cs = 0.0f;
        for (int c = 0; c < CHUNKS; ++c)
            cs += g_cntp[(b * CHUNKS + c) * Kc + t];
        cnt_s[t] = fmaxf(cs, 1.0f);
    }
    __syncthreads();

    // reduce partial sums: thread t owns 4 consecutive (j,e) slots
    float4 s = make_float4(0.f, 0.f, 0.f, 0.f);
    for (int c = 0; c < CHUNKS; ++c) {
        float4 v = *(const float4*)&g_part[((size_t)(b * CHUNKS + c)) * (Kc * Ec) + t * 4];
        s.x += v.x; s.y += v.y; s.z += v.z; s.w += v.w;
    }
    const float inv = 1.0f / cnt_s[t >> 4];
    sm[t * 4 + 0] = s.x * inv;
    sm[t * 4 + 1] = s.y * inv;
    sm[t * 4 + 2] = s.z * inv;
    sm[t * 4 + 3] = s.w * inv;
    __syncthreads();

    if (t < Kc) {
        float ss = 0.0f;
#pragma unroll
        for (int e = 0; e < Ec; ++e) {
            float v = sm[t * Ec + e];
            ss += v * v;
        }
        snm[t] = 1.0f / (fmaxf(sqrtf(ss), EPSF) * TEMPc);
    }
    __syncthreads();

    // warp w handles sample s=w; lane l handles channels 2l, 2l+1
    const int w = t >> 5;
    const int l = t & 31;
    const int pix = pos[(b * Kc + k) * Sc + w];

    const float z0 = emb[((size_t)(b * Ec + 2 * l)) * HWC + pix];
    const float z1 = emb[((size_t)(b * Ec + 2 * l + 1)) * HWC + pix];

    float ss = z0 * z0 + z1 * z1;
#pragma unroll
    for (int off = 16; off > 0; off >>= 1)
        ss += __shfl_xor_sync(0xffffffffu, ss, off);
    const float inz = 1.0f / fmaxf(sqrtf(ss), EPSF);

    float sims[Kc];
    float mx = -1e30f;
#pragma unroll
    for (int c = 0; c < Kc; ++c) {
        float d = z0 * sm[c * Ec + 2 * l] + z1 * sm[c * Ec + 2 * l + 1];
#pragma unroll
        for (int off = 16; off > 0; off >>= 1)
            d += __shfl_xor_sync(0xffffffffu, d, off);
        sims[c] = d * inz * snm[c];
        mx = fmaxf(mx, sims[c]);
    }
    float se = 0.0f;
#pragma unroll
    for (int c = 0; c < Kc; ++c) se += expf(sims[c] - mx);
    const float term = (mx + logf(se)) - sims[k];

    if (l == 0) term_s[w] = term;
    __syncthreads();
    if (t == 0)
        g_lterm[blockIdx.x] = term_s[0] + term_s[1] + term_s[2] + term_s[3];
}

// ---------------------------------------------------------------------------
// Final kernel: one warp reduces the 64 per-(b,k) terms into out[0].
// ---------------------------------------------------------------------------
__global__ void final_kernel(float* __restrict__ out)
{
    const int t = threadIdx.x;   // 32 threads
    float v = g_lterm[t] + g_lterm[t + 32];
#pragma unroll
    for (int off = 16; off > 0; off >>= 1)
        v += __shfl_xor_sync(0xffffffffu, v, off);
    if (t == 0) out[0] = v * (1.0f / 256.0f);
}

// ---------------------------------------------------------------------------
// Pattern [sums, loss, final]: 0-based launch idx 3 (= ncu capture slot)
// is the sums kernel of the second call.
// ---------------------------------------------------------------------------
extern "C" void kernel_launch(void* const* d_in, const int* in_sizes, int n_in,
                              void* d_out, int out_size)
{
    const float* emb   = (const float*)d_in[0];  // [8,64,256,256] f32
    const float* masks = (const float*)d_in[1];  // [8,8,256,256] f32
    const int*   pos   = (const int*)d_in[2];    // [8,8,4] i32

    // Attribute set (not an allocation); idempotent, executes immediately.
    cudaFuncSetAttribute(sums_kernel,
                         cudaFuncAttributeMaxDynamicSharedMemorySize, SMEM_TOTAL);

    sums_kernel<<<Bc * CHUNKS, 256, SMEM_TOTAL>>>(emb, masks);
    loss_kernel<<<Bc * Kc, 128>>>(emb, pos);
    final_kernel<<<1, 32>>>((float*)d_out);
}

// round 15
// speedup vs baseline: 1.4361x; 1.0045x over previous
#include <cuda_runtime.h>
#include <math.h>

#define HWC    65536
#define Bc     8
#define Ec     64
#define Kc     8
#define Sc     4
#define CHUNKS 54            // chunks per image; 8*54 = 432 blocks ~= 2.92/SM
#define PIXPC  1216          // pixels per chunk (mult of 64); last chunk: 1088
#define STPX   64            // pixels per pipeline stage
#define EMB_ST (STPX * Ec * 4)          // 16,384 B emb per stage
#define MSK_ST (STPX * Kc * 4)          //  2,048 B mask per stage
#define STAGE  (EMB_ST + MSK_ST)        // 18,432 B per stage
#define NST    4                        // ring depth (73,728 B x 3 CTAs fits 228KB)
#define SMEM_TOTAL (NST * STAGE)        // 73,728 B
#define TEMPc  0.2f
#define EPSF   1e-8f

// Per-chunk partial sums/counts + per-(b,k) loss terms. Plain stores (slot per
// block) -> no atomics, no zeroing, no cross-replay state.
__device__ float g_part[Bc * CHUNKS * Kc * Ec];   // [gblk][k][e]
__device__ float g_cntp[Bc * CHUNKS * Kc];        // [gblk][k]
__device__ float g_lterm[Bc * Kc];                // per-(b,k) summed terms

// Packed fp32x2 helpers
#define FFMA2(acc, m, v) \
    asm("fma.rn.f32x2 %0, %1, %2, %0;" : "+l"(acc) : "l"(m), "l"(v))
#define ADDX2(d, a, b) \
    asm("add.rn.f32x2 %0, %1, %2;" : "=l"(d) : "l"(a), "l"(b))
#define PACK2(d, lo, hi) \
    asm("mov.b64 %0, {%1, %2};" : "=l"(d) : "f"(lo), "f"(hi))
#define UNPACK2(lo, hi, s) \
    asm("mov.b64 {%0, %1}, %2;" : "=f"(lo), "=f"(hi) : "l"(s))

#define CP_ASYNC16(sp, gp) \
    asm volatile("cp.async.cg.shared.global [%0], [%1], 16;" :: "r"(sp), "l"(gp))
#define CP_COMMIT() asm volatile("cp.async.commit_group;")
#define CP_WAIT2()  asm volatile("cp.async.wait_group 2;")

// ---------------------------------------------------------------------------
// Sums kernel, 3 CTAs/SM. 4-stage cp.async ring, ONE barrier per stage:
//   wait_group 2 -> syncthreads -> issue(s+3) -> compute(s)
// The refill targets slot (s-1)%4, which every warp finished reading before
// this iteration's sync -> the post-compute barrier is gone. Up to 3 stages
// (54 KB/CTA, ~162 KB/SM) stay in flight during compute.
// ---------------------------------------------------------------------------
__global__ __launch_bounds__(256, 3) void sums_kernel(
    const float* __restrict__ emb,    // [B,E,HW]
    const float* __restrict__ masks)  // [B,K,HW]
{
    extern __shared__ __align__(16) unsigned char smraw[];

    const int tid   = threadIdx.x;
    const int b     = blockIdx.x / CHUNKS;
    const int chunk = blockIdx.x % CHUNKS;
    const int gblk  = blockIdx.x;
    const int n0    = chunk * PIXPC;
    const int npix  = (HWC - n0 < PIXPC) ? (HWC - n0) : PIXPC;  // 1216 or 1088
    const int nst   = npix >> 6;                                 // 19 or 17

    const int e2 = tid >> 3;    // 0..31 -> channels 2*e2, 2*e2+1
    const int g  = tid & 7;     // 0..7  -> pixels g*4..g*4+3 per 32-px window
    const int w  = tid >> 5;    // warp id == class owned for counting

    unsigned long long acc[Kc][2];
#pragma unroll
    for (int j = 0; j < Kc; ++j) { acc[j][0] = 0ull; acc[j][1] = 0ull; }
    unsigned long long cnt = 0ull;

    const float* eb = emb   + (size_t)b * Ec * HWC + n0;
    const float* mb = masks + (size_t)b * Kc * HWC + n0;
    const unsigned sm_u32 = (unsigned)__cvta_generic_to_shared(smraw);

    // One stage: emb 1024x16B chunks (4/thread) + mask 128x16B chunks
    // (threads 0..127). smem emb layout [ch][64px]; mask [cls][64px].
#define ISSUE_STAGE(st) do {                                                 \
        const int sl_ = (st) & (NST - 1);                                    \
        const unsigned sb_ = sm_u32 + sl_ * STAGE;                           \
        const float* gb_ = eb + (st) * STPX;                                 \
        _Pragma("unroll")                                                    \
        for (int r_ = 0; r_ < 4; ++r_) {                                     \
            int idx_ = r_ * 256 + tid;                                       \
            int ch_  = idx_ >> 4;                                            \
            int seg_ = idx_ & 15;                                            \
            CP_ASYNC16(sb_ + idx_ * 16, gb_ + (size_t)ch_ * HWC + seg_ * 4); \
        }                                                                    \
        if (tid < 128) {                                                     \
            int k_   = tid >> 4;                                             \
            int seg_ = tid & 15;                                             \
            CP_ASYNC16(sb_ + EMB_ST + tid * 16,                              \
                       mb + (st) * STPX + (size_t)k_ * HWC + seg_ * 4);      \
        }                                                                    \
    } while (0)

    // ---- prologue: issue stages 0..2 (3 groups) -------------------------
    ISSUE_STAGE(0); CP_COMMIT();
    ISSUE_STAGE(1); CP_COMMIT();
    ISSUE_STAGE(2); CP_COMMIT();

    // ---- pipelined compute over 64-px stages, one barrier each ----------
    for (int s = 0; s < nst; ++s) {
        CP_WAIT2();            // all but newest 2 groups done -> stage s ready
        __syncthreads();       // visibility of stage s; slot (s-1)%4 free

        if (s + 3 < nst) ISSUE_STAGE(s + 3);
        CP_COMMIT();           // always commit (empty at tail keeps invariant)

        const unsigned char* base = smraw + (s & (NST - 1)) * STAGE;
        const float* se = (const float*)base + (2 * e2) * STPX + g * 4;
        const ulonglong2* sm = (const ulonglong2*)(base + EMB_ST);  // [cls][16]

#pragma unroll
        for (int h = 0; h < 2; ++h) {
            float4 v0 = *(const float4*)(se + h * 32);
            float4 v1 = *(const float4*)(se + STPX + h * 32);
            unsigned long long a0, a1, c0, c1;
            PACK2(a0, v0.x, v0.y); PACK2(a1, v0.z, v0.w);
            PACK2(c0, v1.x, v1.y); PACK2(c1, v1.z, v1.w);
            const int mi = h * 8 + g;   // 16B units within a class row
#pragma unroll
            for (int j = 0; j < Kc; ++j) {
                ulonglong2 mm = sm[j * 16 + mi];
                FFMA2(acc[j][0], mm.x, a0);
                FFMA2(acc[j][0], mm.y, a1);
                FFMA2(acc[j][1], mm.x, c0);
                FFMA2(acc[j][1], mm.y, c1);
            }
            // counts: warp w owns class w (1 broadcast LDS + 2 packed adds)
            ulonglong2 mw = sm[w * 16 + mi];
            ADDX2(cnt, cnt, mw.x);
            ADDX2(cnt, cnt, mw.y);
        }
    }

    // ---- flush sums: reduce over the 8 g-lanes (lane bits 0..2) ---------
#pragma unroll
    for (int j = 0; j < Kc; ++j)
#pragma unroll
        for (int c = 0; c < 2; ++c) {
            unsigned long long a = acc[j][c], o;
            o = __shfl_xor_sync(0xffffffffu, a, 1); ADDX2(a, a, o);
            o = __shfl_xor_sync(0xffffffffu, a, 2); ADDX2(a, a, o);
            o = __shfl_xor_sync(0xffffffffu, a, 4); ADDX2(a, a, o);
            acc[j][c] = a;
        }
    if (g == 0) {
#pragma unroll
        for (int j = 0; j < Kc; ++j)
#pragma unroll
            for (int c = 0; c < 2; ++c) {
                float lo, hi;
                UNPACK2(lo, hi, acc[j][c]);
                g_part[(size_t)gblk * (Kc * Ec) + j * Ec + 2 * e2 + c] = lo + hi;
            }
    }

    // ---- flush counts: reduce cnt over the warp, /4 lane duplication ----
    {
        unsigned long long a = cnt, o;
        o = __shfl_xor_sync(0xffffffffu, a, 1);  ADDX2(a, a, o);
        o = __shfl_xor_sync(0xffffffffu, a, 2);  ADDX2(a, a, o);
        o = __shfl_xor_sync(0xffffffffu, a, 4);  ADDX2(a, a, o);
        o = __shfl_xor_sync(0xffffffffu, a, 8);  ADDX2(a, a, o);
        o = __shfl_xor_sync(0xffffffffu, a, 16); ADDX2(a, a, o);
        if ((tid & 31) == 0) {
            float lo, hi;
            UNPACK2(lo, hi, a);
            g_cntp[gblk * Kc + w] = (lo + hi) * 0.25f;
        }
    }
#undef ISSUE_STAGE
}

// ---------------------------------------------------------------------------
// Loss kernel: 64 blocks (one per (b,k)), 128 threads. Plain-stores its
// per-(b,k) term sum into g_lterm (no atomics on out).
// ---------------------------------------------------------------------------
__global__ __launch_bounds__(128, 8) void loss_kernel(
    const float* __restrict__ emb,   // [B,E,HW]
    const int*   __restrict__ pos)   // [B,K,S]
{
    __shared__ float sm[Kc * Ec];    // means for this b
    __shared__ float snm[Kc];        // 1/(max(||mean||,eps)*TEMP)
    __shared__ float cnt_s[Kc];
    __shared__ float term_s[Sc];

    const int t = threadIdx.x;
    const int b = blockIdx.x >> 3;
    const int k = blockIdx.x & 7;

    if (t < Kc) {
        float cs = 0.0f;
        for (int c = 0; c < CHUNKS; ++c)
            cs += g_cntp[(b * CHUNKS + c) * Kc + t];
        cnt_s[t] = fmaxf(cs, 1.0f);
    }
    __syncthreads();

    // reduce partial sums: thread t owns 4 consecutive (j,e) slots
    float4 s = make_float4(0.f, 0.f, 0.f, 0.f);
    for (int c = 0; c < CHUNKS; ++c) {
        float4 v = *(const float4*)&g_part[((size_t)(b * CHUNKS + c)) * (Kc * Ec) + t * 4];
        s.x += v.x; s.y += v.y; s.z += v.z; s.w += v.w;
    }
    const float inv = 1.0f / cnt_s[t >> 4];
    sm[t * 4 + 0] = s.x * inv;
    sm[t * 4 + 1] = s.y * inv;
    sm[t * 4 + 2] = s.z * inv;
    sm[t * 4 + 3] = s.w * inv;
    __syncthreads();

    if (t < Kc) {
        float ss = 0.0f;
#pragma unroll
        for (int e = 0; e < Ec; ++e) {
            float v = sm[t * Ec + e];
            ss += v * v;
        }
        snm[t] = 1.0f / (fmaxf(sqrtf(ss), EPSF) * TEMPc);
    }
    __syncthreads();

    // warp w handles sample s=w; lane l handles channels 2l, 2l+1
    const int w = t >> 5;
    const int l = t & 31;
    const int pix = pos[(b * Kc + k) * Sc + w];

    const float z0 = emb[((size_t)(b * Ec + 2 * l)) * HWC + pix];
    const float z1 = emb[((size_t)(b * Ec + 2 * l + 1)) * HWC + pix];

    float ss = z0 * z0 + z1 * z1;
#pragma unroll
    for (int off = 16; off > 0; off >>= 1)
        ss += __shfl_xor_sync(0xffffffffu, ss, off);
    const float inz = 1.0f / fmaxf(sqrtf(ss), EPSF);

    float sims[Kc];
    float mx = -1e30f;
#pragma unroll
    for (int c = 0; c < Kc; ++c) {
        float d = z0 * sm[c * Ec + 2 * l] + z1 * sm[c * Ec + 2 * l + 1];
#pragma unroll
        for (int off = 16; off > 0; off >>= 1)
            d += __shfl_xor_sync(0xffffffffu, d, off);
        sims[c] = d * inz * snm[c];
        mx = fmaxf(mx, sims[c]);
    }
    float se = 0.0f;
#pragma unroll
    for (int c = 0; c < Kc; ++c) se += expf(sims[c] - mx);
    const float term = (mx + logf(se)) - sims[k];

    if (l == 0) term_s[w] = term;
    __syncthreads();
    if (t == 0)
        g_lterm[blockIdx.x] = term_s[0] + term_s[1] + term_s[2] + term_s[3];
}

// ---------------------------------------------------------------------------
// Final kernel: one warp reduces the 64 per-(b,k) terms into out[0].
// ---------------------------------------------------------------------------
__global__ void final_kernel(float* __restrict__ out)
{
    const int t = threadIdx.x;   // 32 threads
    float v = g_lterm[t] + g_lterm[t + 32];
#pragma unroll
    for (int off = 16; off > 0; off >>= 1)
        v += __shfl_xor_sync(0xffffffffu, v, off);
    if (t == 0) out[0] = v * (1.0f / 256.0f);
}

// ---------------------------------------------------------------------------
// Pattern [sums, loss, final]: 0-based launch idx 3 (= ncu capture slot)
// is the sums kernel of the second call.
// ---------------------------------------------------------------------------
extern "C" void kernel_launch(void* const* d_in, const int* in_sizes, int n_in,
                              void* d_out, int out_size)
{
    const float* emb   = (const float*)d_in[0];  // [8,64,256,256] f32
    const float* masks = (const float*)d_in[1];  // [8,8,256,256] f32
    const int*   pos   = (const int*)d_in[2];    // [8,8,4] i32

    // Attribute set (not an allocation); idempotent, executes immediately.
    cudaFuncSetAttribute(sums_kernel,
                         cudaFuncAttributeMaxDynamicSharedMemorySize, SMEM_TOTAL);

    sums_kernel<<<Bc * CHUNKS, 256, SMEM_TOTAL>>>(emb, masks);
    loss_kernel<<<Bc * Kc, 128>>>(emb, pos);
    final_kernel<<<1, 32>>>((float*)d_out);
}

// round 16
// speedup vs baseline: 1.5776x; 1.0986x over previous
#include <cuda_runtime.h>
#include <math.h>

#define HWC    65536
#define Bc     8
#define Ec     64
#define Kc     8
#define Sc     4
#define CHUNKS 37            // chunks per image; 8*37 = 296 blocks = 2/SM, 1 wave
#define PIXPC  1792          // pixels per chunk (mult of 64); last chunk: 1024
#define STPX   64            // pixels per pipeline stage
#define EMB_ST (STPX * Ec * 4)          // 16,384 B emb per stage
#define MSK_ST (STPX * Kc * 4)          //  2,048 B mask per stage
#define STAGE  (EMB_ST + MSK_ST)        // 18,432 B per stage
#define NST    4                        // ring depth; 73,728 B x 2 CTAs = 147 KB
#define SMEM_TOTAL (NST * STAGE)        // 73,728 B
#define TEMPc  0.2f
#define EPSF   1e-8f

// Per-chunk partial sums/counts + per-(b,k) loss terms. Plain stores (slot per
// block) -> no atomics, no zeroing, no cross-replay state.
__device__ float g_part[Bc * CHUNKS * Kc * Ec];   // [gblk][k][e]
__device__ float g_cntp[Bc * CHUNKS * Kc];        // [gblk][k]
__device__ float g_lterm[Bc * Kc];                // per-(b,k) summed terms

// Packed fp32x2 helpers
#define FFMA2(acc, m, v) \
    asm("fma.rn.f32x2 %0, %1, %2, %0;" : "+l"(acc) : "l"(m), "l"(v))
#define ADDX2(d, a, b) \
    asm("add.rn.f32x2 %0, %1, %2;" : "=l"(d) : "l"(a), "l"(b))
#define PACK2(d, lo, hi) \
    asm("mov.b64 %0, {%1, %2};" : "=l"(d) : "f"(lo), "f"(hi))
#define UNPACK2(lo, hi, s) \
    asm("mov.b64 {%0, %1}, %2;" : "=f"(lo), "=f"(hi) : "l"(s))

#define CP_ASYNC16(sp, gp) \
    asm volatile("cp.async.cg.shared.global [%0], [%1], 16;" :: "r"(sp), "l"(gp))
#define CP_COMMIT() asm volatile("cp.async.commit_group;")
#define CP_WAIT2()  asm volatile("cp.async.wait_group 2;")

// ---------------------------------------------------------------------------
// Sums kernel, 4-channel layout (2 CTAs/SM). Thread = (e4 0..15 -> channels
// 4e4..4e4+3, g 0..15 -> pixels g*4..g*4+3); one pass per 64-px stage.
// Per warp-stage: 4 emb LDS.128 + 8 mask LDS.128 + 1 cnt LDS = 13 LDS
// (vs 22 in the 2-ch layout) feeding 64 packed FFMA2. The mask-read
// redundancy (8 warps x same 2 KB) costs 8 instr/warp-stage instead of 16.
// NST=4 cp.async ring, one barrier per stage, unchanged from R14.
// ---------------------------------------------------------------------------
__global__ __launch_bounds__(256, 2) void sums_kernel(
    const float* __restrict__ emb,    // [B,E,HW]
    const float* __restrict__ masks)  // [B,K,HW]
{
    extern __shared__ __align__(16) unsigned char smraw[];

    const int tid   = threadIdx.x;
    const int b     = blockIdx.x / CHUNKS;
    const int chunk = blockIdx.x % CHUNKS;
    const int gblk  = blockIdx.x;
    const int n0    = chunk * PIXPC;
    const int npix  = (HWC - n0 < PIXPC) ? (HWC - n0) : PIXPC;  // 1792 or 1024
    const int nst   = npix >> 6;                                 // 28 or 16

    const int e4 = tid >> 4;    // 0..15 -> channels 4*e4 .. 4*e4+3
    const int g  = tid & 15;    // 0..15 -> pixels g*4 .. g*4+3 per stage
    const int w  = tid >> 5;    // warp id == class owned for counting

    unsigned long long acc[Kc][4];
#pragma unroll
    for (int j = 0; j < Kc; ++j)
#pragma unroll
        for (int c = 0; c < 4; ++c) acc[j][c] = 0ull;
    unsigned long long cnt = 0ull;

    const float* eb = emb   + (size_t)b * Ec * HWC + n0;
    const float* mb = masks + (size_t)b * Kc * HWC + n0;
    const unsigned sm_u32 = (unsigned)__cvta_generic_to_shared(smraw);

    // One stage: emb 1024x16B chunks (4/thread) + mask 128x16B chunks
    // (threads 0..127). smem emb layout [ch][64px]; mask [cls][64px].
#define ISSUE_STAGE(st) do {                                                 \
        const int sl_ = (st) & (NST - 1);                                    \
        const unsigned sb_ = sm_u32 + sl_ * STAGE;                           \
        const float* gb_ = eb + (st) * STPX;                                 \
        _Pragma("unroll")                                                    \
        for (int r_ = 0; r_ < 4; ++r_) {                                     \
            int idx_ = r_ * 256 + tid;                                       \
            int ch_  = idx_ >> 4;                                            \
            int seg_ = idx_ & 15;                                            \
            CP_ASYNC16(sb_ + idx_ * 16, gb_ + (size_t)ch_ * HWC + seg_ * 4); \
        }                                                                    \
        if (tid < 128) {                                                     \
            int k_   = tid >> 4;                                             \
            int seg_ = tid & 15;                                             \
            CP_ASYNC16(sb_ + EMB_ST + tid * 16,                              \
                       mb + (st) * STPX + (size_t)k_ * HWC + seg_ * 4);      \
        }                                                                    \
    } while (0)

    // ---- prologue: issue stages 0..2 (3 groups) -------------------------
    ISSUE_STAGE(0); CP_COMMIT();
    ISSUE_STAGE(1); CP_COMMIT();
    ISSUE_STAGE(2); CP_COMMIT();

    // ---- pipelined compute over 64-px stages, one barrier each ----------
    for (int s = 0; s < nst; ++s) {
        CP_WAIT2();            // all but newest 2 groups done -> stage s ready
        __syncthreads();       // visibility of stage s; slot (s-1)%4 free

        if (s + 3 < nst) ISSUE_STAGE(s + 3);
        CP_COMMIT();           // always commit (empty at tail keeps invariant)

        const unsigned char* base = smraw + (s & (NST - 1)) * STAGE;
        const float* se = (const float*)base + (4 * e4) * STPX + g * 4;
        const ulonglong2* sm = (const ulonglong2*)(base + EMB_ST);  // [cls][16]

        // 4 channels' pixel quads -> packed pairs
        unsigned long long pl[4], ph[4];
#pragma unroll
        for (int c = 0; c < 4; ++c) {
            float4 v = *(const float4*)(se + c * STPX);
            PACK2(pl[c], v.x, v.y);
            PACK2(ph[c], v.z, v.w);
        }
#pragma unroll
        for (int j = 0; j < Kc; ++j) {
            ulonglong2 mm = sm[j * 16 + g];
#pragma unroll
            for (int c = 0; c < 4; ++c) {
                FFMA2(acc[j][c], mm.x, pl[c]);
                FFMA2(acc[j][c], mm.y, ph[c]);
            }
        }
        // counts: warp w owns class w; lanes 0..15 and 16..31 duplicate (x2)
        ulonglong2 mw = sm[w * 16 + g];
        ADDX2(cnt, cnt, mw.x);
        ADDX2(cnt, cnt, mw.y);
    }

    // ---- flush sums: reduce over the 16 g-lanes (lane bits 0..3) --------
#pragma unroll
    for (int j = 0; j < Kc; ++j)
#pragma unroll
        for (int c = 0; c < 4; ++c) {
            unsigned long long a = acc[j][c], o;
            o = __shfl_xor_sync(0xffffffffu, a, 1); ADDX2(a, a, o);
            o = __shfl_xor_sync(0xffffffffu, a, 2); ADDX2(a, a, o);
            o = __shfl_xor_sync(0xffffffffu, a, 4); ADDX2(a, a, o);
            o = __shfl_xor_sync(0xffffffffu, a, 8); ADDX2(a, a, o);
            acc[j][c] = a;
        }
    if (g == 0) {
        float* gp = &g_part[(size_t)gblk * (Kc * Ec)];
#pragma unroll
        for (int j = 0; j < Kc; ++j) {
            float lo, hi, r[4];
#pragma unroll
            for (int c = 0; c < 4; ++c) {
                UNPACK2(lo, hi, acc[j][c]);
                r[c] = lo + hi;
            }
            *(float4*)(gp + j * Ec + 4 * e4) = make_float4(r[0], r[1], r[2], r[3]);
        }
    }

    // ---- flush counts: reduce over the warp, /2 lane duplication --------
    {
        unsigned long long a = cnt, o;
        o = __shfl_xor_sync(0xffffffffu, a, 1);  ADDX2(a, a, o);
        o = __shfl_xor_sync(0xffffffffu, a, 2);  ADDX2(a, a, o);
        o = __shfl_xor_sync(0xffffffffu, a, 4);  ADDX2(a, a, o);
        o = __shfl_xor_sync(0xffffffffu, a, 8);  ADDX2(a, a, o);
        o = __shfl_xor_sync(0xffffffffu, a, 16); ADDX2(a, a, o);
        if ((tid & 31) == 0) {
            float lo, hi;
            UNPACK2(lo, hi, a);
            g_cntp[gblk * Kc + w] = (lo + hi) * 0.5f;
        }
    }
#undef ISSUE_STAGE
}

// ---------------------------------------------------------------------------
// Loss kernel: 64 blocks (one per (b,k)), 128 threads. Plain-stores its
// per-(b,k) term sum into g_lterm (no atomics on out).
// ---------------------------------------------------------------------------
__global__ __launch_bounds__(128, 8) void loss_kernel(
    const float* __restrict__ emb,   // [B,E,HW]
    const int*   __restrict__ pos)   // [B,K,S]
{
    __shared__ float sm[Kc * Ec];    // means for this b
    __shared__ float snm[Kc];        // 1/(max(||mean||,eps)*TEMP)
    __shared__ float cnt_s[Kc];
    __shared__ float term_s[Sc];

    const int t = threadIdx.x;
    const int b = blockIdx.x >> 3;
    const int k = blockIdx.x & 7;

    if (t < Kc) {
        float cs = 0.0f;
        for (int c = 0; c < CHUNKS; ++c)
            cs += g_cntp[(b * CHUNKS + c) * Kc + t];
        cnt_s[t] = fmaxf(cs, 1.0f);
    }
    __syncthreads();

    // reduce partial sums: thread t owns 4 consecutive (j,e) slots
    float4 s = make_float4(0.f, 0.f, 0.f, 0.f);
    for (int c = 0; c < CHUNKS; ++c) {
        float4 v = *(const float4*)&g_part[((size_t)(b * CHUNKS + c)) * (Kc * Ec) + t * 4];
        s.x += v.x; s.y += v.y; s.z += v.z; s.w += v.w;
    }
    const float inv = 1.0f / cnt_s[t >> 4];
    sm[t * 4 + 0] = s.x * inv;
    sm[t * 4 + 1] = s.y * inv;
    sm[t * 4 + 2] = s.z * inv;
    sm[t * 4 + 3] = s.w * inv;
    __syncthreads();

    if (t < Kc) {
        float ss = 0.0f;
#pragma unroll
        for (int e = 0; e < Ec; ++e) {
            float v = sm[t * Ec + e];
            ss += v * v;
        }
        snm[t] = 1.0f / (fmaxf(sqrtf(ss), EPSF) * TEMPc);
    }
    __syncthreads();

    // warp w handles sample s=w; lane l handles channels 2l, 2l+1
    const int w = t >> 5;
    const int l = t & 31;
    const int pix = pos[(b * Kc + k) * Sc + w];

    const float z0 = emb[((size_t)(b * Ec + 2 * l)) * HWC + pix];
    const float z1 = emb[((size_t)(b * Ec + 2 * l + 1)) * HWC + pix];

    float ss = z0 * z0 + z1 * z1;
#pragma unroll
    for (int off = 16; off > 0; off >>= 1)
        ss += __shfl_xor_sync(0xffffffffu, ss, off);
    const float inz = 1.0f / fmaxf(sqrtf(ss), EPSF);

    float sims[Kc];
    float mx = -1e30f;
#pragma unroll
    for (int c = 0; c < Kc; ++c) {
        float d = z0 * sm[c * Ec + 2 * l] + z1 * sm[c * Ec + 2 * l + 1];
#pragma unroll
        for (int off = 16; off > 0; off >>= 1)
            d += __shfl_xor_sync(0xffffffffu, d, off);
        sims[c] = d * inz * snm[c];
        mx = fmaxf(mx, sims[c]);
    }
    float se = 0.0f;
#pragma unroll
    for (int c = 0; c < Kc; ++c) se += expf(sims[c] - mx);
    const float term = (mx + logf(se)) - sims[k];

    if (l == 0) term_s[w] = term;
    __syncthreads();
    if (t == 0)
        g_lterm[blockIdx.x] = term_s[0] + term_s[1] + term_s[2] + term_s[3];
}

// ---------------------------------------------------------------------------
// Final kernel: one warp reduces the 64 per-(b,k) terms into out[0].
// ---------------------------------------------------------------------------
__global__ void final_kernel(float* __restrict__ out)
{
    const int t = threadIdx.x;   // 32 threads
    float v = g_lterm[t] + g_lterm[t + 32];
#pragma unroll
    for (int off = 16; off > 0; off >>= 1)
        v += __shfl_xor_sync(0xffffffffu, v, off);
    if (t == 0) out[0] = v * (1.0f / 256.0f);
}

// ---------------------------------------------------------------------------
// Pattern [sums, loss, final]: 0-based launch idx 3 (= ncu capture slot)
// is the sums kernel of the second call.
// ---------------------------------------------------------------------------
extern "C" void kernel_launch(void* const* d_in, const int* in_sizes, int n_in,
                              void* d_out, int out_size)
{
    const float* emb   = (const float*)d_in[0];  // [8,64,256,256] f32
    const float* masks = (const float*)d_in[1];  // [8,8,256,256] f32
    const int*   pos   = (const int*)d_in[2];    // [8,8,4] i32

    // Attribute set (not an allocation); idempotent, executes immediately.
    cudaFuncSetAttribute(sums_kernel,
                         cudaFuncAttributeMaxDynamicSharedMemorySize, SMEM_TOTAL);

    sums_kernel<<<Bc * CHUNKS, 256, SMEM_TOTAL>>>(emb, masks);
    loss_kernel<<<Bc * Kc, 128>>>(emb, pos);
    final_kernel<<<1, 32>>>((float*)d_out);
}

// round 17
// speedup vs baseline: 1.5789x; 1.0008x over previous
#include <cuda_runtime.h>
#include <math.h>

#define HWC    65536
#define Bc     8
#define Ec     64
#define Kc     8
#define Sc     4
#define CHUNKS 37            // chunks per image; 8*37 = 296 blocks = 2/SM, 1 wave
#define PIXPC  1792          // pixels per chunk (mult of 128); last chunk: 1024
#define STPX   128           // pixels per pipeline stage
#define EMB_ST (STPX * Ec * 4)          // 32,768 B emb per stage
#define MSK_ST (STPX * Kc * 4)          //  4,096 B mask per stage
#define STAGE  (EMB_ST + MSK_ST)        // 36,864 B per stage
#define NST    3                        // ring depth; 110,592 B x 2 CTAs fits
#define SMEM_TOTAL (NST * STAGE)        // 110,592 B
#define TEMPc  0.2f
#define EPSF   1e-8f

// Per-chunk partial sums/counts + per-(b,k) loss terms. Plain stores (slot per
// block) -> no atomics, no zeroing, no cross-replay state.
__device__ float g_part[Bc * CHUNKS * Kc * Ec];   // [gblk][k][e]
__device__ float g_cntp[Bc * CHUNKS * Kc];        // [gblk][k]
__device__ float g_lterm[Bc * Kc];                // per-(b,k) summed terms

// Packed fp32x2 helpers
#define FFMA2(acc, m, v) \
    asm("fma.rn.f32x2 %0, %1, %2, %0;" : "+l"(acc) : "l"(m), "l"(v))
#define ADDX2(d, a, b) \
    asm("add.rn.f32x2 %0, %1, %2;" : "=l"(d) : "l"(a), "l"(b))
#define PACK2(d, lo, hi) \
    asm("mov.b64 %0, {%1, %2};" : "=l"(d) : "f"(lo), "f"(hi))
#define UNPACK2(lo, hi, s) \
    asm("mov.b64 {%0, %1}, %2;" : "=f"(lo), "=f"(hi) : "l"(s))

#define CP_ASYNC16(sp, gp) \
    asm volatile("cp.async.cg.shared.global [%0], [%1], 16;" :: "r"(sp), "l"(gp))
#define CP_COMMIT() asm volatile("cp.async.commit_group;")
#define CP_WAIT1()  asm volatile("cp.async.wait_group 1;")

// ---------------------------------------------------------------------------
// Sums kernel, 4-channel layout (2 CTAs/SM), 128-px stages, NST=3 ring,
// ONE barrier per 128 px (half of R16's):
//   wait_group 1 -> syncthreads -> issue(s+2) -> compute(s) [2 x 64-px halves]
// The refill targets slot (s+2)%3 = (s-1)%3, drained by every warp before
// this iteration's sync. Two 36.8 KB stages stay in flight during compute.
// ---------------------------------------------------------------------------
__global__ __launch_bounds__(256, 2) void sums_kernel(
    const float* __restrict__ emb,    // [B,E,HW]
    const float* __restrict__ masks)  // [B,K,HW]
{
    extern __shared__ __align__(16) unsigned char smraw[];

    const int tid   = threadIdx.x;
    const int b     = blockIdx.x / CHUNKS;
    const int chunk = blockIdx.x % CHUNKS;
    const int gblk  = blockIdx.x;
    const int n0    = chunk * PIXPC;
    const int npix  = (HWC - n0 < PIXPC) ? (HWC - n0) : PIXPC;  // 1792 or 1024
    const int nst   = npix >> 7;                                 // 14 or 8

    const int e4 = tid >> 4;    // 0..15 -> channels 4*e4 .. 4*e4+3
    const int g  = tid & 15;    // 0..15 -> pixels g*4 .. g*4+3 per 64-px half
    const int w  = tid >> 5;    // warp id == class owned for counting

    unsigned long long acc[Kc][4];
#pragma unroll
    for (int j = 0; j < Kc; ++j)
#pragma unroll
        for (int c = 0; c < 4; ++c) acc[j][c] = 0ull;
    unsigned long long cnt = 0ull;

    const float* eb = emb   + (size_t)b * Ec * HWC + n0;
    const float* mb = masks + (size_t)b * Kc * HWC + n0;
    const unsigned sm_u32 = (unsigned)__cvta_generic_to_shared(smraw);

    // One stage: emb 2048x16B chunks (8/thread) + mask 256x16B chunks
    // (1/thread). smem emb layout [ch][128px]; mask [cls][128px].
#define ISSUE_STAGE(st) do {                                                 \
        const int sl_ = (st) % NST;                                          \
        const unsigned sb_ = sm_u32 + sl_ * STAGE;                           \
        const float* gb_ = eb + (st) * STPX;                                 \
        _Pragma("unroll")                                                    \
        for (int r_ = 0; r_ < 8; ++r_) {                                     \
            int idx_ = r_ * 256 + tid;                                       \
            int ch_  = idx_ >> 5;                                            \
            int seg_ = idx_ & 31;                                            \
            CP_ASYNC16(sb_ + idx_ * 16, gb_ + (size_t)ch_ * HWC + seg_ * 4); \
        }                                                                    \
        {                                                                    \
            int k_   = tid >> 5;                                             \
            int seg_ = tid & 31;                                             \
            CP_ASYNC16(sb_ + EMB_ST + tid * 16,                              \
                       mb + (st) * STPX + (size_t)k_ * HWC + seg_ * 4);      \
        }                                                                    \
    } while (0)

    // ---- prologue: issue stages 0..1 (2 groups) -------------------------
    ISSUE_STAGE(0); CP_COMMIT();
    ISSUE_STAGE(1); CP_COMMIT();

    // ---- pipelined compute over 128-px stages, one barrier each ---------
    for (int s = 0; s < nst; ++s) {
        CP_WAIT1();            // all but newest 1 group done -> stage s ready
        __syncthreads();       // visibility of stage s; slot (s-1)%3 free

        if (s + 2 < nst) ISSUE_STAGE(s + 2);
        CP_COMMIT();           // always commit (empty at tail keeps invariant)

        const unsigned char* base = smraw + (s % NST) * STAGE;
        const float* seb = (const float*)base + (4 * e4) * STPX + g * 4;
        const ulonglong2* sm = (const ulonglong2*)(base + EMB_ST);  // [cls][32]

#pragma unroll
        for (int h2 = 0; h2 < 2; ++h2) {
            const float* se = seb + h2 * 64;
            // 4 channels' pixel quads -> packed pairs
            unsigned long long pl[4], ph[4];
#pragma unroll
            for (int c = 0; c < 4; ++c) {
                float4 v = *(const float4*)(se + c * STPX);
                PACK2(pl[c], v.x, v.y);
                PACK2(ph[c], v.z, v.w);
            }
            const int mi = h2 * 16 + g;     // 16B units within a class row
#pragma unroll
            for (int j = 0; j < Kc; ++j) {
                ulonglong2 mm = sm[j * 32 + mi];
#pragma unroll
                for (int c = 0; c < 4; ++c) {
                    FFMA2(acc[j][c], mm.x, pl[c]);
                    FFMA2(acc[j][c], mm.y, ph[c]);
                }
            }
            // counts: warp w owns class w; lane halves duplicate (x2)
            ulonglong2 mw = sm[w * 32 + mi];
            ADDX2(cnt, cnt, mw.x);
            ADDX2(cnt, cnt, mw.y);
        }
    }

    // ---- flush sums: reduce over the 16 g-lanes (lane bits 0..3) --------
#pragma unroll
    for (int j = 0; j < Kc; ++j)
#pragma unroll
        for (int c = 0; c < 4; ++c) {
            unsigned long long a = acc[j][c], o;
            o = __shfl_xor_sync(0xffffffffu, a, 1); ADDX2(a, a, o);
            o = __shfl_xor_sync(0xffffffffu, a, 2); ADDX2(a, a, o);
            o = __shfl_xor_sync(0xffffffffu, a, 4); ADDX2(a, a, o);
            o = __shfl_xor_sync(0xffffffffu, a, 8); ADDX2(a, a, o);
            acc[j][c] = a;
        }
    if (g == 0) {
        float* gp = &g_part[(size_t)gblk * (Kc * Ec)];
#pragma unroll
        for (int j = 0; j < Kc; ++j) {
            float lo, hi, r[4];
#pragma unroll
            for (int c = 0; c < 4; ++c) {
                UNPACK2(lo, hi, acc[j][c]);
                r[c] = lo + hi;
            }
            *(float4*)(gp + j * Ec + 4 * e4) = make_float4(r[0], r[1], r[2], r[3]);
        }
    }

    // ---- flush counts: reduce over the warp, /2 lane duplication --------
    {
        unsigned long long a = cnt, o;
        o = __shfl_xor_sync(0xffffffffu, a, 1);  ADDX2(a, a, o);
        o = __shfl_xor_sync(0xffffffffu, a, 2);  ADDX2(a, a, o);
        o = __shfl_xor_sync(0xffffffffu, a, 4);  ADDX2(a, a, o);
        o = __shfl_xor_sync(0xffffffffu, a, 8);  ADDX2(a, a, o);
        o = __shfl_xor_sync(0xffffffffu, a, 16); ADDX2(a, a, o);
        if ((tid & 31) == 0) {
            float lo, hi;
            UNPACK2(lo, hi, a);
            g_cntp[gblk * Kc + w] = (lo + hi) * 0.5f;
        }
    }
#undef ISSUE_STAGE
}

// ---------------------------------------------------------------------------
// Loss kernel: 64 blocks (one per (b,k)), 128 threads. Plain-stores its
// per-(b,k) term sum into g_lterm (no atomics on out).
// ---------------------------------------------------------------------------
__global__ __launch_bounds__(128, 8) void loss_kernel(
    const float* __restrict__ emb,   // [B,E,HW]
    const int*   __restrict__ pos)   // [B,K,S]
{
    __shared__ float sm[Kc * Ec];    // means for this b
    __shared__ float snm[Kc];        // 1/(max(||mean||,eps)*TEMP)
    __shared__ float cnt_s[Kc];
    __shared__ float term_s[Sc];

    const int t = threadIdx.x;
    const int b = blockIdx.x >> 3;
    const int k = blockIdx.x & 7;

    if (t < Kc) {
        float cs = 0.0f;
        for (int c = 0; c < CHUNKS; ++c)
            cs += g_cntp[(b * CHUNKS + c) * Kc + t];
        cnt_s[t] = fmaxf(cs, 1.0f);
    }
    __syncthreads();

    // reduce partial sums: thread t owns 4 consecutive (j,e) slots
    float4 s = make_float4(0.f, 0.f, 0.f, 0.f);
    for (int c = 0; c < CHUNKS; ++c) {
        float4 v = *(const float4*)&g_part[((size_t)(b * CHUNKS + c)) * (Kc * Ec) + t * 4];
        s.x += v.x; s.y += v.y; s.z += v.z; s.w += v.w;
    }
    const float inv = 1.0f / cnt_s[t >> 4];
    sm[t * 4 + 0] = s.x * inv;
    sm[t * 4 + 1] = s.y * inv;
    sm[t * 4 + 2] = s.z * inv;
    sm[t * 4 + 3] = s.w * inv;
    __syncthreads();

    if (t < Kc) {
        float ss = 0.0f;
#pragma unroll
        for (int e = 0; e < Ec; ++e) {
            float v = sm[t * Ec + e];
            ss += v * v;
        }
        snm[t] = 1.0f / (fmaxf(sqrtf(ss), EPSF) * TEMPc);
    }
    __syncthreads();

    // warp w handles sample s=w; lane l handles channels 2l, 2l+1
    const int w = t >> 5;
    const int l = t & 31;
    const int pix = pos[(b * Kc + k) * Sc + w];

    const float z0 = emb[((size_t)(b * Ec + 2 * l)) * HWC + pix];
    const float z1 = emb[((size_t)(b * Ec + 2 * l + 1)) * HWC + pix];

    float ss = z0 * z0 + z1 * z1;
#pragma unroll
    for (int off = 16; off > 0; off >>= 1)
        ss += __shfl_xor_sync(0xffffffffu, ss, off);
    const float inz = 1.0f / fmaxf(sqrtf(ss), EPSF);

    float sims[Kc];
    float mx = -1e30f;
#pragma unroll
    for (int c = 0; c < Kc; ++c) {
        float d = z0 * sm[c * Ec + 2 * l] + z1 * sm[c * Ec + 2 * l + 1];
#pragma unroll
        for (int off = 16; off > 0; off >>= 1)
            d += __shfl_xor_sync(0xffffffffu, d, off);
        sims[c] = d * inz * snm[c];
        mx = fmaxf(mx, sims[c]);
    }
    float se = 0.0f;
#pragma unroll
    for (int c = 0; c < Kc; ++c) se += expf(sims[c] - mx);
    const float term = (mx + logf(se)) - sims[k];

    if (l == 0) term_s[w] = term;
    __syncthreads();
    if (t == 0)
        g_lterm[blockIdx.x] = term_s[0] + term_s[1] + term_s[2] + term_s[3];
}

// ---------------------------------------------------------------------------
// Final kernel: one warp reduces the 64 per-(b,k) terms into out[0].
// ---------------------------------------------------------------------------
__global__ void final_kernel(float* __restrict__ out)
{
    const int t = threadIdx.x;   // 32 threads
    float v = g_lterm[t] + g_lterm[t + 32];
#pragma unroll
    for (int off = 16; off > 0; off >>= 1)
        v += __shfl_xor_sync(0xffffffffu, v, off);
    if (t == 0) out[0] = v * (1.0f / 256.0f);
}

// ---------------------------------------------------------------------------
// Pattern [sums, loss, final]: 0-based launch idx 3 (= ncu capture slot)
// is the sums kernel of the second call.
// ---------------------------------------------------------------------------
extern "C" void kernel_launch(void* const* d_in, const int* in_sizes, int n_in,
                              void* d_out, int out_size)
{
    const float* emb   = (const float*)d_in[0];  // [8,64,256,256] f32
    const float* masks = (const float*)d_in[1];  // [8,8,256,256] f32
    const int*   pos   = (const int*)d_in[2];    // [8,8,4] i32

    // Attribute set (not an allocation); idempotent, executes immediately.
    cudaFuncSetAttribute(sums_kernel,
                         cudaFuncAttributeMaxDynamicSharedMemorySize, SMEM_TOTAL);

    sums_kernel<<<Bc * CHUNKS, 256, SMEM_TOTAL>>>(emb, masks);
    loss_kernel<<<Bc * Kc, 128>>>(emb, pos);
    final_kernel<<<1, 32>>>((float*)d_out);
}